// round 6
// baseline (speedup 1.0000x reference)
#include <cuda_runtime.h>
#include <math.h>

#define T_SEQ  1024
#define DMODEL 4096
#define NHEAD  32
#define DNOPE  128
#define DROPE  64
#define DHEAD  192   // DNOPE + DROPE
#define DV     128
#define QRANK  1536
#define KVRANK 512
#define IFF    11008
#define EPSV   1e-6f
#define SCALEV 0.07216878364870323f  // 192^-0.5

// ---------------- scratch (static device arrays; no runtime allocation) ----
__device__ float g_x   [T_SEQ * DMODEL];        // rmsnorm(hidden)
__device__ float g_qa  [T_SEQ * QRANK];         // x @ w_q_a^T
__device__ float g_qan [T_SEQ * QRANK];         // rmsnorm(q_a)
__device__ float g_q   [T_SEQ * NHEAD * DHEAD]; // q (nope|pe), pe roped in place
__device__ float g_ckv [T_SEQ * (KVRANK + DROPE)];
__device__ float g_cn  [T_SEQ * KVRANK];
__device__ float g_kv  [T_SEQ * NHEAD * (DNOPE + DV)];
__device__ float g_kf  [T_SEQ * NHEAD * DHEAD]; // k_full
__device__ float g_sc  [(long long)NHEAD * T_SEQ * T_SEQ]; // scores / probs
__device__ float g_ctx [T_SEQ * NHEAD * DV];
__device__ float g_hres[T_SEQ * DMODEL];
__device__ float g_x2  [T_SEQ * DMODEL];
__device__ float g_gu  [T_SEQ * 2 * IFF];
__device__ float g_y   [T_SEQ * IFF];

// ---------------- GEMM (TN): C[m,n] = sum_k A[m,k] * B[n,k] -----------------
// grid = (ceil(N/128), M/128, batch); 256 threads; optional residual R (uses ldc)
__global__ void __launch_bounds__(256) gemm_tn(
    const float* __restrict__ A, int lda, long long sA,
    const float* __restrict__ B, int ldb, long long sB,
    float*       __restrict__ C, int ldc, long long sC,
    const float* __restrict__ R,
    int N, int K)
{
    const int BK = 8;
    __shared__ float As[BK][128];
    __shared__ float Bs[BK][128];
    long long z = blockIdx.z;
    A += z * sA; B += z * sB; C += z * sC;
    int m0 = blockIdx.y * 128, n0 = blockIdx.x * 128;
    int tid = threadIdx.x;
    int lr = tid >> 1, lc = (tid & 1) << 2;   // loader: row, col4
    int tx = tid & 15, ty = tid >> 4;         // compute: 16x16 threads, 8x8 each

    float acc[8][8];
#pragma unroll
    for (int i = 0; i < 8; i++)
#pragma unroll
        for (int j = 0; j < 8; j++) acc[i][j] = 0.f;

    const float* Ap = A + (long long)(m0 + lr) * lda + lc;
    const float* Bp = B + (long long)(n0 + lr) * ldb + lc;
    bool bok = (n0 + lr) < N;

    for (int k0 = 0; k0 < K; k0 += BK) {
        float4 av = *(const float4*)(Ap + k0);
        float4 bv = bok ? *(const float4*)(Bp + k0) : make_float4(0.f, 0.f, 0.f, 0.f);
        As[lc + 0][lr] = av.x; As[lc + 1][lr] = av.y;
        As[lc + 2][lr] = av.z; As[lc + 3][lr] = av.w;
        Bs[lc + 0][lr] = bv.x; Bs[lc + 1][lr] = bv.y;
        Bs[lc + 2][lr] = bv.z; Bs[lc + 3][lr] = bv.w;
        __syncthreads();
#pragma unroll
        for (int k = 0; k < BK; k++) {
            float a[8], b[8];
#pragma unroll
            for (int i = 0; i < 8; i++) a[i] = As[k][ty * 8 + i];
#pragma unroll
            for (int j = 0; j < 8; j++) b[j] = Bs[k][tx * 8 + j];
#pragma unroll
            for (int i = 0; i < 8; i++)
#pragma unroll
                for (int j = 0; j < 8; j++) acc[i][j] += a[i] * b[j];
        }
        __syncthreads();
    }

#pragma unroll
    for (int i = 0; i < 8; i++) {
        int row = m0 + ty * 8 + i;
#pragma unroll
        for (int j = 0; j < 8; j++) {
            int col = n0 + tx * 8 + j;
            if (col < N) {
                float v = acc[i][j];
                if (R) v += R[(long long)row * ldc + col];
                C[(long long)row * ldc + col] = v;
            }
        }
    }
}

// ---------------- GEMM (NN): C[m,n] = sum_k A[m,k] * B[k,n], N == 128 -------
// grid = (1, M/128, batch)
__global__ void __launch_bounds__(256) gemm_nn128(
    const float* __restrict__ A, int lda, long long sA,
    const float* __restrict__ B, int ldb, long long sB,
    float*       __restrict__ C, int ldc, long long sC,
    int K)
{
    const int BK = 8;
    __shared__ float As[BK][128];
    __shared__ float Bs[BK][128];
    long long z = blockIdx.z;
    A += z * sA; B += z * sB; C += z * sC;
    int m0 = blockIdx.y * 128;
    int tid = threadIdx.x;
    int lr = tid >> 1, lc = (tid & 1) << 2;
    int vr = tid >> 5, vc = (tid & 31) << 2;
    int tx = tid & 15, ty = tid >> 4;

    float acc[8][8];
#pragma unroll
    for (int i = 0; i < 8; i++)
#pragma unroll
        for (int j = 0; j < 8; j++) acc[i][j] = 0.f;

    const float* Ap = A + (long long)(m0 + lr) * lda + lc;

    for (int k0 = 0; k0 < K; k0 += BK) {
        float4 av = *(const float4*)(Ap + k0);
        float4 bv = *(const float4*)(B + (long long)(k0 + vr) * ldb + vc);
        As[lc + 0][lr] = av.x; As[lc + 1][lr] = av.y;
        As[lc + 2][lr] = av.z; As[lc + 3][lr] = av.w;
        *(float4*)&Bs[vr][vc] = bv;
        __syncthreads();
#pragma unroll
        for (int k = 0; k < BK; k++) {
            float a[8], b[8];
#pragma unroll
            for (int i = 0; i < 8; i++) a[i] = As[k][ty * 8 + i];
#pragma unroll
            for (int j = 0; j < 8; j++) b[j] = Bs[k][tx * 8 + j];
#pragma unroll
            for (int i = 0; i < 8; i++)
#pragma unroll
                for (int j = 0; j < 8; j++) acc[i][j] += a[i] * b[j];
        }
        __syncthreads();
    }

#pragma unroll
    for (int i = 0; i < 8; i++) {
        int row = m0 + ty * 8 + i;
#pragma unroll
        for (int j = 0; j < 8; j++)
            C[(long long)row * ldc + tx * 8 + j] = acc[i][j];
    }
}

// ---------------- RMSNorm: one block per row --------------------------------
__global__ void __launch_bounds__(256) rmsnorm_k(
    const float* __restrict__ in, int ldin,
    const float* __restrict__ w,
    float* __restrict__ out, int ldout, int cols)
{
    int r = blockIdx.x;
    const float* xr = in + (long long)r * ldin;
    float* orow = out + (long long)r * ldout;
    float s = 0.f;
    for (int i = threadIdx.x; i < cols; i += 256) { float a = xr[i]; s += a * a; }
#pragma unroll
    for (int o = 16; o; o >>= 1) s += __shfl_xor_sync(0xffffffffu, s, o);
    __shared__ float sred[8];
    __shared__ float srs;
    if ((threadIdx.x & 31) == 0) sred[threadIdx.x >> 5] = s;
    __syncthreads();
    if (threadIdx.x == 0) {
        float tot = 0.f;
#pragma unroll
        for (int i = 0; i < 8; i++) tot += sred[i];
        srs = rsqrtf(tot / (float)cols + EPSV);
    }
    __syncthreads();
    float rs = srs;
    for (int i = threadIdx.x; i < cols; i += 256)
        orow[i] = xr[i] * rs * w[i];
}

// ---------------- RoPE on q_pe, in place ------------------------------------
// interleave_to_half + rope:  out[i]=in[2i]*c-in[2i+1]*s ; out[i+32]=in[2i]*s+in[2i+1]*c
// grid (T, 4), block 256: one warp per head
__global__ void __launch_bounds__(256) rope_q(
    float* __restrict__ q, const float* __restrict__ cosb, const float* __restrict__ sinb)
{
    int t = blockIdx.x;
    int h = blockIdx.y * 8 + (threadIdx.x >> 5);
    int i = threadIdx.x & 31;
    float* p = q + ((long long)t * NHEAD + h) * DHEAD + DNOPE;
    float a = p[2 * i], b = p[2 * i + 1];
    float c = cosb[t * 32 + i], s = sinb[t * 32 + i];
    __syncwarp();
    p[i]      = a * c - b * s;
    p[i + 32] = a * s + b * c;
}

// ---------------- assemble k_full: k_nope | broadcast(roped k_pe) -----------
__global__ void __launch_bounds__(256) build_kfull(
    const float* __restrict__ ckv, const float* __restrict__ kv,
    float* __restrict__ kf,
    const float* __restrict__ cosb, const float* __restrict__ sinb)
{
    int t = blockIdx.x;
    __shared__ float kpe[DROPE];
    if (threadIdx.x < 32) {
        int i = threadIdx.x;
        const float* kp = ckv + (long long)t * (KVRANK + DROPE) + KVRANK;
        float a = kp[2 * i], b = kp[2 * i + 1];
        float c = cosb[t * 32 + i], s = sinb[t * 32 + i];
        kpe[i]      = a * c - b * s;
        kpe[i + 32] = a * s + b * c;
    }
    __syncthreads();
    for (int idx = threadIdx.x; idx < NHEAD * DNOPE; idx += 256) {
        int h = idx >> 7, d = idx & 127;
        kf[((long long)t * NHEAD + h) * DHEAD + d] =
            kv[((long long)t * NHEAD + h) * (DNOPE + DV) + d];
    }
    for (int idx = threadIdx.x; idx < NHEAD * DROPE; idx += 256) {
        int h = idx >> 6, d = idx & 63;
        kf[((long long)t * NHEAD + h) * DHEAD + DNOPE + d] = kpe[d];
    }
}

// ---------------- causal softmax (scale fused), in place --------------------
// grid (T, H), block 256; row length T = 4*256, kept in registers
__global__ void __launch_bounds__(256) softmax_causal(float* __restrict__ S)
{
    int t = blockIdx.x;
    long long h = blockIdx.y;
    float* row = S + (h * T_SEQ + t) * (long long)T_SEQ;
    int n = t + 1;
    int tid = threadIdx.x;
    float v[4];
#pragma unroll
    for (int j = 0; j < 4; j++) {
        int i = tid + j * 256;
        v[j] = (i < n) ? row[i] * SCALEV : -3.0e38f;
    }
    float m = fmaxf(fmaxf(v[0], v[1]), fmaxf(v[2], v[3]));
#pragma unroll
    for (int o = 16; o; o >>= 1) m = fmaxf(m, __shfl_xor_sync(0xffffffffu, m, o));
    __shared__ float sred[8];
    __shared__ float sres;
    if ((tid & 31) == 0) sred[tid >> 5] = m;
    __syncthreads();
    if (tid == 0) {
        float x = sred[0];
#pragma unroll
        for (int i = 1; i < 8; i++) x = fmaxf(x, sred[i]);
        sres = x;
    }
    __syncthreads();
    m = sres;
    __syncthreads();
    float s = 0.f;
#pragma unroll
    for (int j = 0; j < 4; j++) { v[j] = __expf(v[j] - m); s += v[j]; }
#pragma unroll
    for (int o = 16; o; o >>= 1) s += __shfl_xor_sync(0xffffffffu, s, o);
    if ((tid & 31) == 0) sred[tid >> 5] = s;
    __syncthreads();
    if (tid == 0) {
        float x = 0.f;
#pragma unroll
        for (int i = 0; i < 8; i++) x += sred[i];
        sres = x;
    }
    __syncthreads();
    float inv = 1.f / sres;
#pragma unroll
    for (int j = 0; j < 4; j++) {
        int i = tid + j * 256;
        row[i] = v[j] * inv;   // masked lanes: exp underflowed to 0
    }
}

// ---------------- silu(gate) * up -------------------------------------------
__global__ void __launch_bounds__(256) silu_mul(
    const float* __restrict__ gu, float* __restrict__ y)
{
    long long idx = (long long)blockIdx.x * 256 + threadIdx.x;  // grid sized exactly
    int t = (int)(idx / IFF);
    int i = (int)(idx % IFF);
    float g = gu[(long long)t * (2 * IFF) + i];
    float u = gu[(long long)t * (2 * IFF) + IFF + i];
    y[idx] = g / (1.f + __expf(-g)) * u;
}

// ---------------- launch ----------------------------------------------------
extern "C" void kernel_launch(void* const* d_in, const int* in_sizes, int n_in,
                              void* d_out, int out_size)
{
    const float* hidden    = (const float*)d_in[0];
    const float* cosb      = (const float*)d_in[1];
    const float* sinb      = (const float*)d_in[2];
    const float* w_ln_in   = (const float*)d_in[3];
    const float* w_q_a     = (const float*)d_in[4];
    const float* w_q_ln    = (const float*)d_in[5];
    const float* w_q_b     = (const float*)d_in[6];
    const float* w_kv_a    = (const float*)d_in[7];
    const float* w_kv_ln   = (const float*)d_in[8];
    const float* w_kv_b    = (const float*)d_in[9];
    const float* w_o       = (const float*)d_in[10];
    const float* w_ln_post = (const float*)d_in[11];
    const float* w_gate_up = (const float*)d_in[12];
    const float* w_down    = (const float*)d_in[13];
    float* out = (float*)d_out;

    float *x, *qa, *qan, *q, *ckv, *cn, *kv, *kf, *sc, *ctx, *hres, *x2, *gu, *y;
    cudaGetSymbolAddress((void**)&x,    g_x);
    cudaGetSymbolAddress((void**)&qa,   g_qa);
    cudaGetSymbolAddress((void**)&qan,  g_qan);
    cudaGetSymbolAddress((void**)&q,    g_q);
    cudaGetSymbolAddress((void**)&ckv,  g_ckv);
    cudaGetSymbolAddress((void**)&cn,   g_cn);
    cudaGetSymbolAddress((void**)&kv,   g_kv);
    cudaGetSymbolAddress((void**)&kf,   g_kf);
    cudaGetSymbolAddress((void**)&sc,   g_sc);
    cudaGetSymbolAddress((void**)&ctx,  g_ctx);
    cudaGetSymbolAddress((void**)&hres, g_hres);
    cudaGetSymbolAddress((void**)&x2,   g_x2);
    cudaGetSymbolAddress((void**)&gu,   g_gu);
    cudaGetSymbolAddress((void**)&y,    g_y);

    // 1. x = rmsnorm(hidden)
    rmsnorm_k<<<T_SEQ, 256>>>(hidden, DMODEL, w_ln_in, x, DMODEL, DMODEL);
    // 2. q_a = x @ w_q_a^T
    gemm_tn<<<dim3(QRANK / 128, T_SEQ / 128, 1), 256>>>(
        x, DMODEL, 0, w_q_a, DMODEL, 0, qa, QRANK, 0, nullptr, QRANK, DMODEL);
    // 3. q_a = rmsnorm(q_a)
    rmsnorm_k<<<T_SEQ, 256>>>(qa, QRANK, w_q_ln, qan, QRANK, QRANK);
    // 4. q = q_a @ w_q_b^T  -> [T, H, 192]
    gemm_tn<<<dim3((NHEAD * DHEAD) / 128, T_SEQ / 128, 1), 256>>>(
        qan, QRANK, 0, w_q_b, QRANK, 0, q, NHEAD * DHEAD, 0, nullptr, NHEAD * DHEAD, QRANK);
    // 5. ckv = x @ w_kv_a^T  -> [T, 576]
    gemm_tn<<<dim3(5, T_SEQ / 128, 1), 256>>>(
        x, DMODEL, 0, w_kv_a, DMODEL, 0, ckv, KVRANK + DROPE, 0, nullptr, KVRANK + DROPE, DMODEL);
    // 6. c_n = rmsnorm(ckv[:, :512])
    rmsnorm_k<<<T_SEQ, 256>>>(ckv, KVRANK + DROPE, w_kv_ln, cn, KVRANK, KVRANK);
    // 7. kv = c_n @ w_kv_b^T -> [T, H, 256]
    gemm_tn<<<dim3((NHEAD * 256) / 128, T_SEQ / 128, 1), 256>>>(
        cn, KVRANK, 0, w_kv_b, KVRANK, 0, kv, NHEAD * 256, 0, nullptr, NHEAD * 256, KVRANK);
    // 8. rope q_pe in place
    rope_q<<<dim3(T_SEQ, NHEAD / 8), 256>>>(q, cosb, sinb);
    // 9. k_full
    build_kfull<<<T_SEQ, 256>>>(ckv, kv, kf, cosb, sinb);
    // 10. scores[h] = q[:,h,:] @ k_full[:,h,:]^T   (batched over heads)
    gemm_tn<<<dim3(T_SEQ / 128, T_SEQ / 128, NHEAD), 256>>>(
        q, NHEAD * DHEAD, (long long)DHEAD,
        kf, NHEAD * DHEAD, (long long)DHEAD,
        sc, T_SEQ, (long long)T_SEQ * T_SEQ,
        nullptr, T_SEQ, DHEAD);
    // 11. causal softmax with scale
    softmax_causal<<<dim3(T_SEQ, NHEAD), 256>>>(sc);
    // 12. ctx[:,h,:] = probs[h] @ v[:,h,:]
    gemm_nn128<<<dim3(1, T_SEQ / 128, NHEAD), 256>>>(
        sc, T_SEQ, (long long)T_SEQ * T_SEQ,
        kv + DNOPE, NHEAD * 256, 256LL,
        ctx, NHEAD * DV, (long long)DV,
        T_SEQ);
    // 13. h_res = ctx @ w_o^T + hidden
    gemm_tn<<<dim3(DMODEL / 128, T_SEQ / 128, 1), 256>>>(
        ctx, DMODEL, 0, w_o, DMODEL, 0, hres, DMODEL, 0, hidden, DMODEL, DMODEL);
    // 14. x2 = rmsnorm(h_res)
    rmsnorm_k<<<T_SEQ, 256>>>(hres, DMODEL, w_ln_post, x2, DMODEL, DMODEL);
    // 15. gu = x2 @ w_gate_up^T -> [T, 2*IFF]
    gemm_tn<<<dim3((2 * IFF) / 128, T_SEQ / 128, 1), 256>>>(
        x2, DMODEL, 0, w_gate_up, DMODEL, 0, gu, 2 * IFF, 0, nullptr, 2 * IFF, DMODEL);
    // 16. y = silu(gate) * up
    silu_mul<<<(T_SEQ * IFF) / 256, 256>>>(gu, y);
    // 17. out = y @ w_down^T + h_res
    gemm_tn<<<dim3(DMODEL / 128, T_SEQ / 128, 1), 256>>>(
        y, IFF, 0, w_down, IFF, 0, out, DMODEL, 0, hres, DMODEL, IFF);
}

// round 8
// speedup vs baseline: 4.9658x; 4.9658x over previous
#include <cuda_runtime.h>
#include <math.h>

#define T_SEQ  1024
#define DMODEL 4096
#define NHEAD  32
#define DNOPE  128
#define DROPE  64
#define DHEAD  192   // DNOPE + DROPE
#define DV     128
#define QRANK  1536
#define KVRANK 512
#define IFF    11008
#define EPSV   1e-6f
#define SCALEV 0.07216878364870323f  // 192^-0.5

// ---------------- scratch (static device arrays; no runtime allocation) ----
__device__ float g_x   [T_SEQ * DMODEL];
__device__ float g_qa  [T_SEQ * QRANK];
__device__ float g_qan [T_SEQ * QRANK];
__device__ float g_q   [T_SEQ * NHEAD * DHEAD];
__device__ float g_ckv [T_SEQ * (KVRANK + DROPE)];
__device__ float g_cn  [T_SEQ * KVRANK];
__device__ float g_kv  [T_SEQ * NHEAD * (DNOPE + DV)];
__device__ float g_kf  [T_SEQ * NHEAD * DHEAD];
__device__ float g_vt  [NHEAD * DV * T_SEQ];            // V transposed per head
__device__ float g_sc  [(long long)NHEAD * T_SEQ * T_SEQ];
__device__ float g_ctx [T_SEQ * NHEAD * DV];
__device__ float g_hres[T_SEQ * DMODEL];
__device__ float g_x2  [T_SEQ * DMODEL];
__device__ float g_gu  [T_SEQ * 2 * IFF];
__device__ float g_y   [T_SEQ * IFF];

// ---------------- tf32 helpers ----------------------------------------------
__device__ __forceinline__ unsigned f2tf32(float f) {
    unsigned r;
    asm("cvt.rna.tf32.f32 %0, %1;" : "=r"(r) : "f"(f));
    return r;
}

__device__ __forceinline__ void mma8(float c[4], const unsigned a[4], const unsigned b[2]) {
    asm volatile(
        "mma.sync.aligned.m16n8k8.row.col.f32.tf32.tf32.f32 "
        "{%0,%1,%2,%3},{%4,%5,%6,%7},{%8,%9},{%0,%1,%2,%3};\n"
        : "+f"(c[0]), "+f"(c[1]), "+f"(c[2]), "+f"(c[3])
        : "r"(a[0]), "r"(a[1]), "r"(a[2]), "r"(a[3]),
          "r"(b[0]), "r"(b[1]));
}

// ---------------- tf32 tensor-core GEMM (TN): C[m,n] = sum_k A[m,k]*B[n,k] --
// 128x128 tile, BK=32, 8 warps (2x4), each warp 64x32 via 4x4 m16n8k8 tiles.
// grid = (ceil(N/128), M/128, batch); optional residual R (uses ldc).
// Requires: M % 128 == 0, K % 32 == 0, K >= 32, row pointers 16B-aligned.
#define SST 36   // shared row stride in floats (128+8): frag loads conflict-free
__global__ void __launch_bounds__(256, 2) gemm_tn_tf32(
    const float* __restrict__ A, int lda, long long sA,
    const float* __restrict__ B, int ldb, long long sB,
    float*       __restrict__ C, int ldc, long long sC,
    const float* __restrict__ R,
    int N, int K)
{
    __shared__ unsigned As[128 * SST];
    __shared__ unsigned Bs[128 * SST];
    long long z = blockIdx.z;
    A += z * sA; B += z * sB; C += z * sC;
    int m0 = blockIdx.y * 128, n0 = blockIdx.x * 128;
    int tid = threadIdx.x;
    int lr = tid >> 1, lcb = (tid & 1) << 4;          // loader: row, col base (0/16)
    int wid = tid >> 5, wm = wid & 1, wn = wid >> 1;  // warp 2x4
    int lane = tid & 31, g = lane >> 2, t = lane & 3;

    float acc[4][4][4];
#pragma unroll
    for (int i = 0; i < 4; i++)
#pragma unroll
        for (int j = 0; j < 4; j++)
#pragma unroll
            for (int e = 0; e < 4; e++) acc[i][j][e] = 0.f;

    const float* Ap = A + (long long)(m0 + lr) * lda;
    bool bok = (n0 + lr) < N;
    const float* Bp = B + (long long)(n0 + lr) * ldb;

    for (int k0 = 0; k0 < K; k0 += 32) {
#pragma unroll
        for (int j = 0; j < 4; j++) {
            int c = lcb + j * 4;
            float4 av = *(const float4*)(Ap + k0 + c);
            uint4 ua;
            ua.x = f2tf32(av.x); ua.y = f2tf32(av.y);
            ua.z = f2tf32(av.z); ua.w = f2tf32(av.w);
            *(uint4*)&As[lr * SST + c] = ua;
            float4 bv = bok ? *(const float4*)(Bp + k0 + c)
                            : make_float4(0.f, 0.f, 0.f, 0.f);
            uint4 ub;
            ub.x = f2tf32(bv.x); ub.y = f2tf32(bv.y);
            ub.z = f2tf32(bv.z); ub.w = f2tf32(bv.w);
            *(uint4*)&Bs[lr * SST + c] = ub;
        }
        __syncthreads();
#pragma unroll
        for (int kk = 0; kk < 4; kk++) {
            unsigned a[4][4], b[4][2];
#pragma unroll
            for (int i = 0; i < 4; i++) {
                const unsigned* p = &As[(wm * 64 + i * 16 + g) * SST + kk * 8 + t];
                a[i][0] = p[0];
                a[i][1] = p[8 * SST];
                a[i][2] = p[4];
                a[i][3] = p[8 * SST + 4];
            }
#pragma unroll
            for (int j = 0; j < 4; j++) {
                const unsigned* p = &Bs[(wn * 32 + j * 8 + g) * SST + kk * 8 + t];
                b[j][0] = p[0];
                b[j][1] = p[4];
            }
#pragma unroll
            for (int i = 0; i < 4; i++)
#pragma unroll
                for (int j = 0; j < 4; j++) mma8(acc[i][j], a[i], b[j]);
        }
        __syncthreads();
    }

#pragma unroll
    for (int i = 0; i < 4; i++) {
        int r0 = m0 + wm * 64 + i * 16 + g;
#pragma unroll
        for (int j = 0; j < 4; j++) {
            int c0 = n0 + wn * 32 + j * 8 + 2 * t;
            if (c0 < N) {
                float v0 = acc[i][j][0], v1 = acc[i][j][1];
                float v2 = acc[i][j][2], v3 = acc[i][j][3];
                if (R) {
                    v0 += R[(long long)r0 * ldc + c0];
                    v1 += R[(long long)r0 * ldc + c0 + 1];
                    v2 += R[(long long)(r0 + 8) * ldc + c0];
                    v3 += R[(long long)(r0 + 8) * ldc + c0 + 1];
                }
                float2 w0 = make_float2(v0, v1);
                float2 w1 = make_float2(v2, v3);
                *(float2*)&C[(long long)r0 * ldc + c0] = w0;
                *(float2*)&C[(long long)(r0 + 8) * ldc + c0] = w1;
            }
        }
    }
}

// ---------------- V transpose: vt[h][d][t] = kv[t][h][128+d] ----------------
// treats src as [T=1024][HD=4096] (with per-head offset math), dst [HD][T]
__global__ void __launch_bounds__(256) transpose_v(
    const float* __restrict__ kv, float* __restrict__ vt)
{
    __shared__ float tile[32][33];
    int hd0 = blockIdx.x * 32, t0 = blockIdx.y * 32;
    int x = threadIdx.x & 31, ybase = threadIdx.x >> 5;  // 32x8
    for (int y = ybase; y < 32; y += 8) {
        int hd = hd0 + x, tt = t0 + y;
        tile[y][x] = kv[(long long)tt * (NHEAD * 256) + (hd >> 7) * 256 + DNOPE + (hd & 127)];
    }
    __syncthreads();
    for (int y = ybase; y < 32; y += 8) {
        int hd = hd0 + y, tt = t0 + x;
        vt[(long long)hd * T_SEQ + tt] = tile[x][y];
    }
}

// ---------------- RMSNorm: one block per row --------------------------------
__global__ void __launch_bounds__(256) rmsnorm_k(
    const float* __restrict__ in, int ldin,
    const float* __restrict__ w,
    float* __restrict__ out, int ldout, int cols)
{
    int r = blockIdx.x;
    const float* xr = in + (long long)r * ldin;
    float* orow = out + (long long)r * ldout;
    float s = 0.f;
    for (int i = threadIdx.x; i < cols; i += 256) { float a = xr[i]; s += a * a; }
#pragma unroll
    for (int o = 16; o; o >>= 1) s += __shfl_xor_sync(0xffffffffu, s, o);
    __shared__ float sred[8];
    __shared__ float srs;
    if ((threadIdx.x & 31) == 0) sred[threadIdx.x >> 5] = s;
    __syncthreads();
    if (threadIdx.x == 0) {
        float tot = 0.f;
#pragma unroll
        for (int i = 0; i < 8; i++) tot += sred[i];
        srs = rsqrtf(tot / (float)cols + EPSV);
    }
    __syncthreads();
    float rs = srs;
    for (int i = threadIdx.x; i < cols; i += 256)
        orow[i] = xr[i] * rs * w[i];
}

// ---------------- RoPE on q_pe, in place ------------------------------------
__global__ void __launch_bounds__(256) rope_q(
    float* __restrict__ q, const float* __restrict__ cosb, const float* __restrict__ sinb)
{
    int t = blockIdx.x;
    int h = blockIdx.y * 8 + (threadIdx.x >> 5);
    int i = threadIdx.x & 31;
    float* p = q + ((long long)t * NHEAD + h) * DHEAD + DNOPE;
    float a = p[2 * i], b = p[2 * i + 1];
    float c = cosb[t * 32 + i], s = sinb[t * 32 + i];
    __syncwarp();
    p[i]      = a * c - b * s;
    p[i + 32] = a * s + b * c;
}

// ---------------- assemble k_full: k_nope | broadcast(roped k_pe) -----------
__global__ void __launch_bounds__(256) build_kfull(
    const float* __restrict__ ckv, const float* __restrict__ kv,
    float* __restrict__ kf,
    const float* __restrict__ cosb, const float* __restrict__ sinb)
{
    int t = blockIdx.x;
    __shared__ float kpe[DROPE];
    if (threadIdx.x < 32) {
        int i = threadIdx.x;
        const float* kp = ckv + (long long)t * (KVRANK + DROPE) + KVRANK;
        float a = kp[2 * i], b = kp[2 * i + 1];
        float c = cosb[t * 32 + i], s = sinb[t * 32 + i];
        kpe[i]      = a * c - b * s;
        kpe[i + 32] = a * s + b * c;
    }
    __syncthreads();
    for (int idx = threadIdx.x; idx < NHEAD * DNOPE; idx += 256) {
        int h = idx >> 7, d = idx & 127;
        kf[((long long)t * NHEAD + h) * DHEAD + d] =
            kv[((long long)t * NHEAD + h) * (DNOPE + DV) + d];
    }
    for (int idx = threadIdx.x; idx < NHEAD * DROPE; idx += 256) {
        int h = idx >> 6, d = idx & 63;
        kf[((long long)t * NHEAD + h) * DHEAD + DNOPE + d] = kpe[d];
    }
}

// ---------------- causal softmax (scale fused), in place --------------------
__global__ void __launch_bounds__(256) softmax_causal(float* __restrict__ S)
{
    int t = blockIdx.x;
    long long h = blockIdx.y;
    float* row = S + (h * T_SEQ + t) * (long long)T_SEQ;
    int n = t + 1;
    int tid = threadIdx.x;
    float v[4];
#pragma unroll
    for (int j = 0; j < 4; j++) {
        int i = tid + j * 256;
        v[j] = (i < n) ? row[i] * SCALEV : -3.0e38f;
    }
    float m = fmaxf(fmaxf(v[0], v[1]), fmaxf(v[2], v[3]));
#pragma unroll
    for (int o = 16; o; o >>= 1) m = fmaxf(m, __shfl_xor_sync(0xffffffffu, m, o));
    __shared__ float sred[8];
    __shared__ float sres;
    if ((tid & 31) == 0) sred[tid >> 5] = m;
    __syncthreads();
    if (tid == 0) {
        float x = sred[0];
#pragma unroll
        for (int i = 1; i < 8; i++) x = fmaxf(x, sred[i]);
        sres = x;
    }
    __syncthreads();
    m = sres;
    __syncthreads();
    float s = 0.f;
#pragma unroll
    for (int j = 0; j < 4; j++) { v[j] = __expf(v[j] - m); s += v[j]; }
#pragma unroll
    for (int o = 16; o; o >>= 1) s += __shfl_xor_sync(0xffffffffu, s, o);
    if ((tid & 31) == 0) sred[tid >> 5] = s;
    __syncthreads();
    if (tid == 0) {
        float x = 0.f;
#pragma unroll
        for (int i = 0; i < 8; i++) x += sred[i];
        sres = x;
    }
    __syncthreads();
    float inv = 1.f / sres;
#pragma unroll
    for (int j = 0; j < 4; j++) {
        int i = tid + j * 256;
        row[i] = v[j] * inv;
    }
}

// ---------------- silu(gate) * up -------------------------------------------
__global__ void __launch_bounds__(256) silu_mul(
    const float* __restrict__ gu, float* __restrict__ y)
{
    long long idx = (long long)blockIdx.x * 256 + threadIdx.x;
    int t = (int)(idx / IFF);
    int i = (int)(idx % IFF);
    float g = gu[(long long)t * (2 * IFF) + i];
    float u = gu[(long long)t * (2 * IFF) + IFF + i];
    y[idx] = g / (1.f + __expf(-g)) * u;
}

// ---------------- launch ----------------------------------------------------
extern "C" void kernel_launch(void* const* d_in, const int* in_sizes, int n_in,
                              void* d_out, int out_size)
{
    const float* hidden    = (const float*)d_in[0];
    const float* cosb      = (const float*)d_in[1];
    const float* sinb      = (const float*)d_in[2];
    const float* w_ln_in   = (const float*)d_in[3];
    const float* w_q_a     = (const float*)d_in[4];
    const float* w_q_ln    = (const float*)d_in[5];
    const float* w_q_b     = (const float*)d_in[6];
    const float* w_kv_a    = (const float*)d_in[7];
    const float* w_kv_ln   = (const float*)d_in[8];
    const float* w_kv_b    = (const float*)d_in[9];
    const float* w_o       = (const float*)d_in[10];
    const float* w_ln_post = (const float*)d_in[11];
    const float* w_gate_up = (const float*)d_in[12];
    const float* w_down    = (const float*)d_in[13];
    float* out = (float*)d_out;

    float *x, *qa, *qan, *q, *ckv, *cn, *kv, *kf, *vt, *sc, *ctx, *hres, *x2, *gu, *y;
    cudaGetSymbolAddress((void**)&x,    g_x);
    cudaGetSymbolAddress((void**)&qa,   g_qa);
    cudaGetSymbolAddress((void**)&qan,  g_qan);
    cudaGetSymbolAddress((void**)&q,    g_q);
    cudaGetSymbolAddress((void**)&ckv,  g_ckv);
    cudaGetSymbolAddress((void**)&cn,   g_cn);
    cudaGetSymbolAddress((void**)&kv,   g_kv);
    cudaGetSymbolAddress((void**)&kf,   g_kf);
    cudaGetSymbolAddress((void**)&vt,   g_vt);
    cudaGetSymbolAddress((void**)&sc,   g_sc);
    cudaGetSymbolAddress((void**)&ctx,  g_ctx);
    cudaGetSymbolAddress((void**)&hres, g_hres);
    cudaGetSymbolAddress((void**)&x2,   g_x2);
    cudaGetSymbolAddress((void**)&gu,   g_gu);
    cudaGetSymbolAddress((void**)&y,    g_y);

    // 1. x = rmsnorm(hidden)
    rmsnorm_k<<<T_SEQ, 256>>>(hidden, DMODEL, w_ln_in, x, DMODEL, DMODEL);
    // 2. q_a = x @ w_q_a^T
    gemm_tn_tf32<<<dim3(QRANK / 128, T_SEQ / 128, 1), 256>>>(
        x, DMODEL, 0, w_q_a, DMODEL, 0, qa, QRANK, 0, nullptr, QRANK, DMODEL);
    // 3. q_a = rmsnorm(q_a)
    rmsnorm_k<<<T_SEQ, 256>>>(qa, QRANK, w_q_ln, qan, QRANK, QRANK);
    // 4. q = q_a @ w_q_b^T  -> [T, H, 192]
    gemm_tn_tf32<<<dim3((NHEAD * DHEAD) / 128, T_SEQ / 128, 1), 256>>>(
        qan, QRANK, 0, w_q_b, QRANK, 0, q, NHEAD * DHEAD, 0, nullptr, NHEAD * DHEAD, QRANK);
    // 5. ckv = x @ w_kv_a^T  -> [T, 576]
    gemm_tn_tf32<<<dim3(5, T_SEQ / 128, 1), 256>>>(
        x, DMODEL, 0, w_kv_a, DMODEL, 0, ckv, KVRANK + DROPE, 0, nullptr, KVRANK + DROPE, DMODEL);
    // 6. c_n = rmsnorm(ckv[:, :512])
    rmsnorm_k<<<T_SEQ, 256>>>(ckv, KVRANK + DROPE, w_kv_ln, cn, KVRANK, KVRANK);
    // 7. kv = c_n @ w_kv_b^T -> [T, H, 256]
    gemm_tn_tf32<<<dim3((NHEAD * 256) / 128, T_SEQ / 128, 1), 256>>>(
        cn, KVRANK, 0, w_kv_b, KVRANK, 0, kv, NHEAD * 256, 0, nullptr, NHEAD * 256, KVRANK);
    // 8. rope q_pe in place
    rope_q<<<dim3(T_SEQ, NHEAD / 8), 256>>>(q, cosb, sinb);
    // 9. k_full
    build_kfull<<<T_SEQ, 256>>>(ckv, kv, kf, cosb, sinb);
    // 9b. vt = V^T per head
    transpose_v<<<dim3((NHEAD * DV) / 32, T_SEQ / 32), 256>>>(kv, vt);
    // 10. scores[h] = q[:,h,:] @ k_full[:,h,:]^T   (batched over heads)
    gemm_tn_tf32<<<dim3(T_SEQ / 128, T_SEQ / 128, NHEAD), 256>>>(
        q, NHEAD * DHEAD, (long long)DHEAD,
        kf, NHEAD * DHEAD, (long long)DHEAD,
        sc, T_SEQ, (long long)T_SEQ * T_SEQ,
        nullptr, T_SEQ, DHEAD);
    // 11. causal softmax with scale
    softmax_causal<<<dim3(T_SEQ, NHEAD), 256>>>(sc);
    // 12. ctx[:,h,:] = probs[h] @ vt[h]^T   (TN, batched over heads)
    gemm_tn_tf32<<<dim3(1, T_SEQ / 128, NHEAD), 256>>>(
        sc, T_SEQ, (long long)T_SEQ * T_SEQ,
        vt, T_SEQ, (long long)DV * T_SEQ,
        ctx, NHEAD * DV, (long long)DV,
        nullptr, DV, T_SEQ);
    // 13. h_res = ctx @ w_o^T + hidden
    gemm_tn_tf32<<<dim3(DMODEL / 128, T_SEQ / 128, 1), 256>>>(
        ctx, DMODEL, 0, w_o, DMODEL, 0, hres, DMODEL, 0, hidden, DMODEL, DMODEL);
    // 14. x2 = rmsnorm(h_res)
    rmsnorm_k<<<T_SEQ, 256>>>(hres, DMODEL, w_ln_post, x2, DMODEL, DMODEL);
    // 15. gu = x2 @ w_gate_up^T -> [T, 2*IFF]
    gemm_tn_tf32<<<dim3((2 * IFF) / 128, T_SEQ / 128, 1), 256>>>(
        x2, DMODEL, 0, w_gate_up, DMODEL, 0, gu, 2 * IFF, 0, nullptr, 2 * IFF, DMODEL);
    // 16. y = silu(gate) * up
    silu_mul<<<(T_SEQ * IFF) / 256, 256>>>(gu, y);
    // 17. out = y @ w_down^T + h_res
    gemm_tn_tf32<<<dim3(DMODEL / 128, T_SEQ / 128, 1), 256>>>(
        y, IFF, 0, w_down, IFF, 0, out, DMODEL, 0, hres, DMODEL, IFF);
}

// round 9
// speedup vs baseline: 5.0076x; 1.0084x over previous
#include <cuda_runtime.h>
#include <math.h>

#define T_SEQ  1024
#define DMODEL 4096
#define NHEAD  32
#define DNOPE  128
#define DROPE  64
#define DHEAD  192   // DNOPE + DROPE
#define DV     128
#define QRANK  1536
#define KVRANK 512
#define IFF    11008
#define EPSV   1e-6f
#define SCALEV 0.07216878364870323f  // 192^-0.5

// ---------------- scratch (static device arrays; no runtime allocation) ----
__device__ float g_x   [T_SEQ * DMODEL];
__device__ float g_qa  [T_SEQ * QRANK];
__device__ float g_qan [T_SEQ * QRANK];
__device__ float g_q   [T_SEQ * NHEAD * DHEAD];
__device__ float g_ckv [T_SEQ * (KVRANK + DROPE)];
__device__ float g_cn  [T_SEQ * KVRANK];
__device__ float g_kv  [T_SEQ * NHEAD * (DNOPE + DV)];
__device__ float g_kf  [T_SEQ * NHEAD * DHEAD];
__device__ float g_vt  [NHEAD * DV * T_SEQ];            // V transposed per head
__device__ float g_sc  [(long long)NHEAD * T_SEQ * T_SEQ];
__device__ float g_ctx [T_SEQ * NHEAD * DV];
__device__ float g_hres[T_SEQ * DMODEL];
__device__ float g_x2  [T_SEQ * DMODEL];
__device__ float g_gu  [T_SEQ * 2 * IFF];
__device__ float g_y   [T_SEQ * IFF];

// ---------------- tf32 helpers ----------------------------------------------
__device__ __forceinline__ unsigned f2tf32(float f) {
    unsigned r;
    asm("cvt.rna.tf32.f32 %0, %1;" : "=r"(r) : "f"(f));
    return r;
}

__device__ __forceinline__ void mma8(float c[4], const unsigned a[4], const unsigned b[2]) {
    asm volatile(
        "mma.sync.aligned.m16n8k8.row.col.f32.tf32.tf32.f32 "
        "{%0,%1,%2,%3},{%4,%5,%6,%7},{%8,%9},{%0,%1,%2,%3};\n"
        : "+f"(c[0]), "+f"(c[1]), "+f"(c[2]), "+f"(c[3])
        : "r"(a[0]), "r"(a[1]), "r"(a[2]), "r"(a[3]),
          "r"(b[0]), "r"(b[1]));
}

__device__ __forceinline__ void cp16(unsigned dst, const void* src, bool pred) {
    asm volatile("cp.async.cg.shared.global [%0], [%1], 16, %2;\n"
                 :: "r"(dst), "l"(src), "r"(pred ? 16 : 0));
}
#define CP_COMMIT() asm volatile("cp.async.commit_group;\n" ::: "memory")
#define CP_WAIT1()  asm volatile("cp.async.wait_group 1;\n" ::: "memory")

// ---------------- tf32 tensor-core GEMM (TN): C[m,n] = sum_k A[m,k]*B[n,k] --
// 128x128 tile, BK=32, 8 warps (2x4), each warp 64x32 via 4x4 m16n8k8 tiles.
// 3-stage cp.async pipeline; raw f32 in shared, cvt.rna at consume.
// grid = (ceil(N/128), M/128, batch); optional residual R (uses ldc).
// Requires: M % 128 == 0, K % 32 == 0, K >= 64, rows 16B-aligned.
// causal: skip blocks fully above diagonal. kcap: clamp K to m0+128.
#define SST    36    // shared row stride in floats: frag loads conflict-free
#define STAGES 3
#define GSMEM_SZ (STAGES * 2 * 128 * SST * 4)

__global__ void __launch_bounds__(256, 2) gemm_tn_tf32(
    const float* __restrict__ A, int lda, long long sA,
    const float* __restrict__ B, int ldb, long long sB,
    float*       __restrict__ C, int ldc, long long sC,
    const float* __restrict__ R,
    int N, int K, int causal, int kcap)
{
    extern __shared__ float sh[];
    float* Asm = sh;                          // [STAGES][128*SST]
    float* Bsm = sh + STAGES * 128 * SST;

    long long z = blockIdx.z;
    A += z * sA; B += z * sB; C += z * sC;
    int m0 = blockIdx.y * 128, n0 = blockIdx.x * 128;
    if (causal && n0 > m0 + 127) return;      // fully-masked score block
    if (kcap) { int kl = m0 + 128; if (kl < K) K = kl; }

    int tid = threadIdx.x;
    int lr = tid >> 1, lcb = (tid & 1) << 4;          // loader: row, col base
    int wid = tid >> 5, wm = wid & 1, wn = wid >> 1;  // warp 2x4
    int lane = tid & 31, g = lane >> 2, t = lane & 3;

    unsigned As_u = (unsigned)__cvta_generic_to_shared(Asm);
    unsigned Bs_u = (unsigned)__cvta_generic_to_shared(Bsm);

    const float* Ap = A + (long long)(m0 + lr) * lda + lcb;
    bool bok = (n0 + lr) < N;
    const float* Bp = B + (long long)(n0 + lr) * ldb + lcb;

    float acc[4][4][4];
#pragma unroll
    for (int i = 0; i < 4; i++)
#pragma unroll
        for (int j = 0; j < 4; j++)
#pragma unroll
            for (int e = 0; e < 4; e++) acc[i][j][e] = 0.f;

    int nk = K >> 5;  // K/32 tiles

    // -- prefetch helper (macro to keep addresses in registers) --
#define PREFETCH(K0, S) do {                                                  \
        unsigned abase = As_u + (((S) * 128 + lr) * SST + lcb) * 4;           \
        unsigned bbase = Bs_u + (((S) * 128 + lr) * SST + lcb) * 4;           \
        const float* ap = Ap + (K0);                                          \
        const float* bp = Bp + (K0);                                          \
        _Pragma("unroll")                                                     \
        for (int j = 0; j < 4; j++) {                                         \
            cp16(abase + j * 16, ap + j * 4, true);                           \
            cp16(bbase + j * 16, bp + j * 4, bok);                            \
        }                                                                     \
    } while (0)

    PREFETCH(0, 0);
    CP_COMMIT();
    if (nk > 1) PREFETCH(32, 1);
    CP_COMMIT();

    for (int it = 0; it < nk; it++) {
        CP_WAIT1();
        __syncthreads();
        if (it + 2 < nk) PREFETCH((it + 2) << 5, (it + 2) % STAGES);
        CP_COMMIT();

        int srow = (it % STAGES) * 128;
#pragma unroll
        for (int kk = 0; kk < 4; kk++) {
            unsigned a[4][4], b[4][2];
#pragma unroll
            for (int i = 0; i < 4; i++) {
                const float* p = &Asm[(srow + wm * 64 + i * 16 + g) * SST + kk * 8 + t];
                a[i][0] = f2tf32(p[0]);
                a[i][1] = f2tf32(p[8 * SST]);
                a[i][2] = f2tf32(p[4]);
                a[i][3] = f2tf32(p[8 * SST + 4]);
            }
#pragma unroll
            for (int j = 0; j < 4; j++) {
                const float* p = &Bsm[(srow + wn * 32 + j * 8 + g) * SST + kk * 8 + t];
                b[j][0] = f2tf32(p[0]);
                b[j][1] = f2tf32(p[4]);
            }
#pragma unroll
            for (int i = 0; i < 4; i++)
#pragma unroll
                for (int j = 0; j < 4; j++) mma8(acc[i][j], a[i], b[j]);
        }
    }

#pragma unroll
    for (int i = 0; i < 4; i++) {
        int r0 = m0 + wm * 64 + i * 16 + g;
#pragma unroll
        for (int j = 0; j < 4; j++) {
            int c0 = n0 + wn * 32 + j * 8 + 2 * t;
            if (c0 < N) {
                float v0 = acc[i][j][0], v1 = acc[i][j][1];
                float v2 = acc[i][j][2], v3 = acc[i][j][3];
                if (R) {
                    v0 += R[(long long)r0 * ldc + c0];
                    v1 += R[(long long)r0 * ldc + c0 + 1];
                    v2 += R[(long long)(r0 + 8) * ldc + c0];
                    v3 += R[(long long)(r0 + 8) * ldc + c0 + 1];
                }
                *(float2*)&C[(long long)r0 * ldc + c0]       = make_float2(v0, v1);
                *(float2*)&C[(long long)(r0 + 8) * ldc + c0] = make_float2(v2, v3);
            }
        }
    }
}

// ---------------- V transpose: vt[h][d][t] = kv[t][h][128+d] ----------------
__global__ void __launch_bounds__(256) transpose_v(
    const float* __restrict__ kv, float* __restrict__ vt)
{
    __shared__ float tile[32][33];
    int hd0 = blockIdx.x * 32, t0 = blockIdx.y * 32;
    int x = threadIdx.x & 31, ybase = threadIdx.x >> 5;  // 32x8
    for (int y = ybase; y < 32; y += 8) {
        int hd = hd0 + x, tt = t0 + y;
        tile[y][x] = kv[(long long)tt * (NHEAD * 256) + (hd >> 7) * 256 + DNOPE + (hd & 127)];
    }
    __syncthreads();
    for (int y = ybase; y < 32; y += 8) {
        int hd = hd0 + y, tt = t0 + x;
        vt[(long long)hd * T_SEQ + tt] = tile[x][y];
    }
}

// ---------------- RMSNorm: one block per row --------------------------------
__global__ void __launch_bounds__(256) rmsnorm_k(
    const float* __restrict__ in, int ldin,
    const float* __restrict__ w,
    float* __restrict__ out, int ldout, int cols)
{
    int r = blockIdx.x;
    const float* xr = in + (long long)r * ldin;
    float* orow = out + (long long)r * ldout;
    float s = 0.f;
    for (int i = threadIdx.x; i < cols; i += 256) { float a = xr[i]; s += a * a; }
#pragma unroll
    for (int o = 16; o; o >>= 1) s += __shfl_xor_sync(0xffffffffu, s, o);
    __shared__ float sred[8];
    __shared__ float srs;
    if ((threadIdx.x & 31) == 0) sred[threadIdx.x >> 5] = s;
    __syncthreads();
    if (threadIdx.x == 0) {
        float tot = 0.f;
#pragma unroll
        for (int i = 0; i < 8; i++) tot += sred[i];
        srs = rsqrtf(tot / (float)cols + EPSV);
    }
    __syncthreads();
    float rs = srs;
    for (int i = threadIdx.x; i < cols; i += 256)
        orow[i] = xr[i] * rs * w[i];
}

// ---------------- RoPE on q_pe, in place ------------------------------------
__global__ void __launch_bounds__(256) rope_q(
    float* __restrict__ q, const float* __restrict__ cosb, const float* __restrict__ sinb)
{
    int t = blockIdx.x;
    int h = blockIdx.y * 8 + (threadIdx.x >> 5);
    int i = threadIdx.x & 31;
    float* p = q + ((long long)t * NHEAD + h) * DHEAD + DNOPE;
    float a = p[2 * i], b = p[2 * i + 1];
    float c = cosb[t * 32 + i], s = sinb[t * 32 + i];
    __syncwarp();
    p[i]      = a * c - b * s;
    p[i + 32] = a * s + b * c;
}

// ---------------- assemble k_full: k_nope | broadcast(roped k_pe) -----------
__global__ void __launch_bounds__(256) build_kfull(
    const float* __restrict__ ckv, const float* __restrict__ kv,
    float* __restrict__ kf,
    const float* __restrict__ cosb, const float* __restrict__ sinb)
{
    int t = blockIdx.x;
    __shared__ float kpe[DROPE];
    if (threadIdx.x < 32) {
        int i = threadIdx.x;
        const float* kp = ckv + (long long)t * (KVRANK + DROPE) + KVRANK;
        float a = kp[2 * i], b = kp[2 * i + 1];
        float c = cosb[t * 32 + i], s = sinb[t * 32 + i];
        kpe[i]      = a * c - b * s;
        kpe[i + 32] = a * s + b * c;
    }
    __syncthreads();
    for (int idx = threadIdx.x; idx < NHEAD * DNOPE; idx += 256) {
        int h = idx >> 7, d = idx & 127;
        kf[((long long)t * NHEAD + h) * DHEAD + d] =
            kv[((long long)t * NHEAD + h) * (DNOPE + DV) + d];
    }
    for (int idx = threadIdx.x; idx < NHEAD * DROPE; idx += 256) {
        int h = idx >> 6, d = idx & 63;
        kf[((long long)t * NHEAD + h) * DHEAD + DNOPE + d] = kpe[d];
    }
}

// ---------------- causal softmax (scale fused), in place --------------------
__global__ void __launch_bounds__(256) softmax_causal(float* __restrict__ S)
{
    int t = blockIdx.x;
    long long h = blockIdx.y;
    float* row = S + (h * T_SEQ + t) * (long long)T_SEQ;
    int n = t + 1;
    int tid = threadIdx.x;
    float v[4];
#pragma unroll
    for (int j = 0; j < 4; j++) {
        int i = tid + j * 256;
        v[j] = (i < n) ? row[i] * SCALEV : -3.0e38f;
    }
    float m = fmaxf(fmaxf(v[0], v[1]), fmaxf(v[2], v[3]));
#pragma unroll
    for (int o = 16; o; o >>= 1) m = fmaxf(m, __shfl_xor_sync(0xffffffffu, m, o));
    __shared__ float sred[8];
    __shared__ float sres;
    if ((tid & 31) == 0) sred[tid >> 5] = m;
    __syncthreads();
    if (tid == 0) {
        float x = sred[0];
#pragma unroll
        for (int i = 1; i < 8; i++) x = fmaxf(x, sred[i]);
        sres = x;
    }
    __syncthreads();
    m = sres;
    __syncthreads();
    float s = 0.f;
#pragma unroll
    for (int j = 0; j < 4; j++) { v[j] = __expf(v[j] - m); s += v[j]; }
#pragma unroll
    for (int o = 16; o; o >>= 1) s += __shfl_xor_sync(0xffffffffu, s, o);
    if ((tid & 31) == 0) sred[tid >> 5] = s;
    __syncthreads();
    if (tid == 0) {
        float x = 0.f;
#pragma unroll
        for (int i = 0; i < 8; i++) x += sred[i];
        sres = x;
    }
    __syncthreads();
    float inv = 1.f / sres;
#pragma unroll
    for (int j = 0; j < 4; j++) {
        int i = tid + j * 256;
        row[i] = v[j] * inv;
    }
}

// ---------------- silu(gate) * up -------------------------------------------
__global__ void __launch_bounds__(256) silu_mul(
    const float* __restrict__ gu, float* __restrict__ y)
{
    long long idx = (long long)blockIdx.x * 256 + threadIdx.x;
    int t = (int)(idx / IFF);
    int i = (int)(idx % IFF);
    float g = gu[(long long)t * (2 * IFF) + i];
    float u = gu[(long long)t * (2 * IFF) + IFF + i];
    y[idx] = g / (1.f + __expf(-g)) * u;
}

// ---------------- launch ----------------------------------------------------
extern "C" void kernel_launch(void* const* d_in, const int* in_sizes, int n_in,
                              void* d_out, int out_size)
{
    const float* hidden    = (const float*)d_in[0];
    const float* cosb      = (const float*)d_in[1];
    const float* sinb      = (const float*)d_in[2];
    const float* w_ln_in   = (const float*)d_in[3];
    const float* w_q_a     = (const float*)d_in[4];
    const float* w_q_ln    = (const float*)d_in[5];
    const float* w_q_b     = (const float*)d_in[6];
    const float* w_kv_a    = (const float*)d_in[7];
    const float* w_kv_ln   = (const float*)d_in[8];
    const float* w_kv_b    = (const float*)d_in[9];
    const float* w_o       = (const float*)d_in[10];
    const float* w_ln_post = (const float*)d_in[11];
    const float* w_gate_up = (const float*)d_in[12];
    const float* w_down    = (const float*)d_in[13];
    float* out = (float*)d_out;

    static int smem_set = 0;
    if (!smem_set) {
        cudaFuncSetAttribute(gemm_tn_tf32,
                             cudaFuncAttributeMaxDynamicSharedMemorySize, GSMEM_SZ);
        smem_set = 1;
    }

    float *x, *qa, *qan, *q, *ckv, *cn, *kv, *kf, *vt, *sc, *ctx, *hres, *x2, *gu, *y;
    cudaGetSymbolAddress((void**)&x,    g_x);
    cudaGetSymbolAddress((void**)&qa,   g_qa);
    cudaGetSymbolAddress((void**)&qan,  g_qan);
    cudaGetSymbolAddress((void**)&q,    g_q);
    cudaGetSymbolAddress((void**)&ckv,  g_ckv);
    cudaGetSymbolAddress((void**)&cn,   g_cn);
    cudaGetSymbolAddress((void**)&kv,   g_kv);
    cudaGetSymbolAddress((void**)&kf,   g_kf);
    cudaGetSymbolAddress((void**)&vt,   g_vt);
    cudaGetSymbolAddress((void**)&sc,   g_sc);
    cudaGetSymbolAddress((void**)&ctx,  g_ctx);
    cudaGetSymbolAddress((void**)&hres, g_hres);
    cudaGetSymbolAddress((void**)&x2,   g_x2);
    cudaGetSymbolAddress((void**)&gu,   g_gu);
    cudaGetSymbolAddress((void**)&y,    g_y);

    // 1. x = rmsnorm(hidden)
    rmsnorm_k<<<T_SEQ, 256>>>(hidden, DMODEL, w_ln_in, x, DMODEL, DMODEL);
    // 2. q_a = x @ w_q_a^T
    gemm_tn_tf32<<<dim3(QRANK / 128, T_SEQ / 128, 1), 256, GSMEM_SZ>>>(
        x, DMODEL, 0, w_q_a, DMODEL, 0, qa, QRANK, 0, nullptr, QRANK, DMODEL, 0, 0);
    // 3. q_a = rmsnorm(q_a)
    rmsnorm_k<<<T_SEQ, 256>>>(qa, QRANK, w_q_ln, qan, QRANK, QRANK);
    // 4. q = q_a @ w_q_b^T  -> [T, H, 192]
    gemm_tn_tf32<<<dim3((NHEAD * DHEAD) / 128, T_SEQ / 128, 1), 256, GSMEM_SZ>>>(
        qan, QRANK, 0, w_q_b, QRANK, 0, q, NHEAD * DHEAD, 0, nullptr, NHEAD * DHEAD, QRANK, 0, 0);
    // 5. ckv = x @ w_kv_a^T  -> [T, 576]
    gemm_tn_tf32<<<dim3(5, T_SEQ / 128, 1), 256, GSMEM_SZ>>>(
        x, DMODEL, 0, w_kv_a, DMODEL, 0, ckv, KVRANK + DROPE, 0, nullptr, KVRANK + DROPE, DMODEL, 0, 0);
    // 6. c_n = rmsnorm(ckv[:, :512])
    rmsnorm_k<<<T_SEQ, 256>>>(ckv, KVRANK + DROPE, w_kv_ln, cn, KVRANK, KVRANK);
    // 7. kv = c_n @ w_kv_b^T -> [T, H, 256]
    gemm_tn_tf32<<<dim3((NHEAD * 256) / 128, T_SEQ / 128, 1), 256, GSMEM_SZ>>>(
        cn, KVRANK, 0, w_kv_b, KVRANK, 0, kv, NHEAD * 256, 0, nullptr, NHEAD * 256, KVRANK, 0, 0);
    // 8. rope q_pe in place
    rope_q<<<dim3(T_SEQ, NHEAD / 8), 256>>>(q, cosb, sinb);
    // 9. k_full
    build_kfull<<<T_SEQ, 256>>>(ckv, kv, kf, cosb, sinb);
    // 9b. vt = V^T per head
    transpose_v<<<dim3((NHEAD * DV) / 32, T_SEQ / 32), 256>>>(kv, vt);
    // 10. scores[h] = q[:,h,:] @ k_full[:,h,:]^T   (batched; causal-skip)
    gemm_tn_tf32<<<dim3(T_SEQ / 128, T_SEQ / 128, NHEAD), 256, GSMEM_SZ>>>(
        q, NHEAD * DHEAD, (long long)DHEAD,
        kf, NHEAD * DHEAD, (long long)DHEAD,
        sc, T_SEQ, (long long)T_SEQ * T_SEQ,
        nullptr, T_SEQ, DHEAD, 1, 0);
    // 11. causal softmax with scale (writes exact zeros above diagonal)
    softmax_causal<<<dim3(T_SEQ, NHEAD), 256>>>(sc);
    // 12. ctx[:,h,:] = probs[h] @ vt[h]^T  (TN, batched; K capped at m0+128)
    gemm_tn_tf32<<<dim3(1, T_SEQ / 128, NHEAD), 256, GSMEM_SZ>>>(
        sc, T_SEQ, (long long)T_SEQ * T_SEQ,
        vt, T_SEQ, (long long)DV * T_SEQ,
        ctx, NHEAD * DV, (long long)DV,
        nullptr, DV, T_SEQ, 0, 1);
    // 13. h_res = ctx @ w_o^T + hidden
    gemm_tn_tf32<<<dim3(DMODEL / 128, T_SEQ / 128, 1), 256, GSMEM_SZ>>>(
        ctx, DMODEL, 0, w_o, DMODEL, 0, hres, DMODEL, 0, hidden, DMODEL, DMODEL, 0, 0);
    // 14. x2 = rmsnorm(h_res)
    rmsnorm_k<<<T_SEQ, 256>>>(hres, DMODEL, w_ln_post, x2, DMODEL, DMODEL);
    // 15. gu = x2 @ w_gate_up^T -> [T, 2*IFF]
    gemm_tn_tf32<<<dim3((2 * IFF) / 128, T_SEQ / 128, 1), 256, GSMEM_SZ>>>(
        x2, DMODEL, 0, w_gate_up, DMODEL, 0, gu, 2 * IFF, 0, nullptr, 2 * IFF, DMODEL, 0, 0);
    // 16. y = silu(gate) * up
    silu_mul<<<(T_SEQ * IFF) / 256, 256>>>(gu, y);
    // 17. out = y @ w_down^T + h_res
    gemm_tn_tf32<<<dim3(DMODEL / 128, T_SEQ / 128, 1), 256, GSMEM_SZ>>>(
        y, IFF, 0, w_down, IFF, 0, out, DMODEL, 0, hres, DMODEL, IFF, 0, 0);
}

// round 10
// speedup vs baseline: 5.0135x; 1.0012x over previous
#include <cuda_runtime.h>
#include <math.h>

#define T_SEQ  1024
#define DMODEL 4096
#define NHEAD  32
#define DNOPE  128
#define DROPE  64
#define DHEAD  192   // DNOPE + DROPE
#define DV     128
#define QRANK  1536
#define KVRANK 512
#define IFF    11008
#define EPSV   1e-6f
#define SCALEV 0.07216878364870323f  // 192^-0.5

// ---------------- scratch (static device arrays; no runtime allocation) ----
__device__ float g_x   [T_SEQ * DMODEL];
__device__ float g_qa  [T_SEQ * QRANK];
__device__ float g_qan [T_SEQ * QRANK];
__device__ float g_q   [T_SEQ * NHEAD * DHEAD];
__device__ float g_ckv [T_SEQ * (KVRANK + DROPE)];
__device__ float g_cn  [T_SEQ * KVRANK];
__device__ float g_kv  [T_SEQ * NHEAD * (DNOPE + DV)];
__device__ float g_kf  [T_SEQ * NHEAD * DHEAD];
__device__ float g_vt  [NHEAD * DV * T_SEQ];            // V transposed per head
__device__ float g_sc  [(long long)NHEAD * T_SEQ * T_SEQ];
__device__ float g_ctx [T_SEQ * NHEAD * DV];
__device__ float g_hres[T_SEQ * DMODEL];
__device__ float g_x2  [T_SEQ * DMODEL];
__device__ float g_gu  [T_SEQ * 2 * IFF];
__device__ float g_y   [T_SEQ * IFF];

// ---------------- tf32 helpers ----------------------------------------------
__device__ __forceinline__ unsigned f2tf32(float f) {
    unsigned r;
    asm("cvt.rna.tf32.f32 %0, %1;" : "=r"(r) : "f"(f));
    return r;
}

__device__ __forceinline__ void mma8(float c[4], const unsigned a[4], const unsigned b[2]) {
    asm volatile(
        "mma.sync.aligned.m16n8k8.row.col.f32.tf32.tf32.f32 "
        "{%0,%1,%2,%3},{%4,%5,%6,%7},{%8,%9},{%0,%1,%2,%3};\n"
        : "+f"(c[0]), "+f"(c[1]), "+f"(c[2]), "+f"(c[3])
        : "r"(a[0]), "r"(a[1]), "r"(a[2]), "r"(a[3]),
          "r"(b[0]), "r"(b[1]));
}

__device__ __forceinline__ void cp16(unsigned dst, const void* src, bool pred) {
    asm volatile("cp.async.cg.shared.global [%0], [%1], 16, %2;\n"
                 :: "r"(dst), "l"(src), "r"(pred ? 16 : 0));
}
#define CP_COMMIT() asm volatile("cp.async.commit_group;\n" ::: "memory")
#define CP_WAIT1()  asm volatile("cp.async.wait_group 1;\n" ::: "memory")

// ---------------- tf32 tensor-core GEMM (TN): C[m,n] = sum_k A[m,k]*B[n,k] --
// 128x128 tile, BK=32, 8 warps (2x4), each warp 64x32 via 4x4 m16n8k8 tiles.
// 3-stage cp.async pipeline; raw f32 in shared, cvt.rna at consume.
// grid = (ceil(N/128), M/128, batch); optional residual R (uses ldc).
// Requires: M % 128 == 0, K % 32 == 0, K >= 64, rows 16B-aligned.
// causal: skip blocks fully above diagonal. kcap: clamp K to m0+128.
#define SST    36    // shared row stride in floats: frag loads conflict-free
#define STAGES 3
#define GSMEM_SZ (STAGES * 2 * 128 * SST * 4)

__global__ void __launch_bounds__(256, 2) gemm_tn_tf32(
    const float* __restrict__ A, int lda, long long sA,
    const float* __restrict__ B, int ldb, long long sB,
    float*       __restrict__ C, int ldc, long long sC,
    const float* __restrict__ R,
    int N, int K, int causal, int kcap)
{
    extern __shared__ float sh[];
    float* Asm = sh;                          // [STAGES][128*SST]
    float* Bsm = sh + STAGES * 128 * SST;

    long long z = blockIdx.z;
    A += z * sA; B += z * sB; C += z * sC;
    int m0 = blockIdx.y * 128, n0 = blockIdx.x * 128;
    if (causal && n0 > m0 + 127) return;      // fully-masked score block
    if (kcap) { int kl = m0 + 128; if (kl < K) K = kl; }

    int tid = threadIdx.x;
    int lr = tid >> 1, lcb = (tid & 1) << 4;          // loader: row, col base
    int wid = tid >> 5, wm = wid & 1, wn = wid >> 1;  // warp 2x4
    int lane = tid & 31, g = lane >> 2, t = lane & 3;

    unsigned As_u = (unsigned)__cvta_generic_to_shared(Asm);
    unsigned Bs_u = (unsigned)__cvta_generic_to_shared(Bsm);

    const float* Ap = A + (long long)(m0 + lr) * lda + lcb;
    bool bok = (n0 + lr) < N;
    const float* Bp = B + (long long)(n0 + lr) * ldb + lcb;

    float acc[4][4][4];
#pragma unroll
    for (int i = 0; i < 4; i++)
#pragma unroll
        for (int j = 0; j < 4; j++)
#pragma unroll
            for (int e = 0; e < 4; e++) acc[i][j][e] = 0.f;

    int nk = K >> 5;  // K/32 tiles

    // -- prefetch helper (macro to keep addresses in registers) --
#define PREFETCH(K0, S) do {                                                  \
        unsigned abase = As_u + (((S) * 128 + lr) * SST + lcb) * 4;           \
        unsigned bbase = Bs_u + (((S) * 128 + lr) * SST + lcb) * 4;           \
        const float* ap = Ap + (K0);                                          \
        const float* bp = Bp + (K0);                                          \
        _Pragma("unroll")                                                     \
        for (int j = 0; j < 4; j++) {                                         \
            cp16(abase + j * 16, ap + j * 4, true);                           \
            cp16(bbase + j * 16, bp + j * 4, bok);                            \
        }                                                                     \
    } while (0)

    PREFETCH(0, 0);
    CP_COMMIT();
    if (nk > 1) PREFETCH(32, 1);
    CP_COMMIT();

    for (int it = 0; it < nk; it++) {
        CP_WAIT1();
        __syncthreads();
        if (it + 2 < nk) PREFETCH((it + 2) << 5, (it + 2) % STAGES);
        CP_COMMIT();

        int srow = (it % STAGES) * 128;
#pragma unroll
        for (int kk = 0; kk < 4; kk++) {
            unsigned a[4][4], b[4][2];
#pragma unroll
            for (int i = 0; i < 4; i++) {
                const float* p = &Asm[(srow + wm * 64 + i * 16 + g) * SST + kk * 8 + t];
                a[i][0] = f2tf32(p[0]);
                a[i][1] = f2tf32(p[8 * SST]);
                a[i][2] = f2tf32(p[4]);
                a[i][3] = f2tf32(p[8 * SST + 4]);
            }
#pragma unroll
            for (int j = 0; j < 4; j++) {
                const float* p = &Bsm[(srow + wn * 32 + j * 8 + g) * SST + kk * 8 + t];
                b[j][0] = f2tf32(p[0]);
                b[j][1] = f2tf32(p[4]);
            }
#pragma unroll
            for (int i = 0; i < 4; i++)
#pragma unroll
                for (int j = 0; j < 4; j++) mma8(acc[i][j], a[i], b[j]);
        }
    }

#pragma unroll
    for (int i = 0; i < 4; i++) {
        int r0 = m0 + wm * 64 + i * 16 + g;
#pragma unroll
        for (int j = 0; j < 4; j++) {
            int c0 = n0 + wn * 32 + j * 8 + 2 * t;
            if (c0 < N) {
                float v0 = acc[i][j][0], v1 = acc[i][j][1];
                float v2 = acc[i][j][2], v3 = acc[i][j][3];
                if (R) {
                    v0 += R[(long long)r0 * ldc + c0];
                    v1 += R[(long long)r0 * ldc + c0 + 1];
                    v2 += R[(long long)(r0 + 8) * ldc + c0];
                    v3 += R[(long long)(r0 + 8) * ldc + c0 + 1];
                }
                *(float2*)&C[(long long)r0 * ldc + c0]       = make_float2(v0, v1);
                *(float2*)&C[(long long)(r0 + 8) * ldc + c0] = make_float2(v2, v3);
            }
        }
    }
}

// ---------------- V transpose: vt[h][d][t] = kv[t][h][128+d] ----------------
__global__ void __launch_bounds__(256) transpose_v(
    const float* __restrict__ kv, float* __restrict__ vt)
{
    __shared__ float tile[32][33];
    int hd0 = blockIdx.x * 32, t0 = blockIdx.y * 32;
    int x = threadIdx.x & 31, ybase = threadIdx.x >> 5;  // 32x8
    for (int y = ybase; y < 32; y += 8) {
        int hd = hd0 + x, tt = t0 + y;
        tile[y][x] = kv[(long long)tt * (NHEAD * 256) + (hd >> 7) * 256 + DNOPE + (hd & 127)];
    }
    __syncthreads();
    for (int y = ybase; y < 32; y += 8) {
        int hd = hd0 + y, tt = t0 + x;
        vt[(long long)hd * T_SEQ + tt] = tile[x][y];
    }
}

// ---------------- RMSNorm: one block per row --------------------------------
__global__ void __launch_bounds__(256) rmsnorm_k(
    const float* __restrict__ in, int ldin,
    const float* __restrict__ w,
    float* __restrict__ out, int ldout, int cols)
{
    int r = blockIdx.x;
    const float* xr = in + (long long)r * ldin;
    float* orow = out + (long long)r * ldout;
    float s = 0.f;
    for (int i = threadIdx.x; i < cols; i += 256) { float a = xr[i]; s += a * a; }
#pragma unroll
    for (int o = 16; o; o >>= 1) s += __shfl_xor_sync(0xffffffffu, s, o);
    __shared__ float sred[8];
    __shared__ float srs;
    if ((threadIdx.x & 31) == 0) sred[threadIdx.x >> 5] = s;
    __syncthreads();
    if (threadIdx.x == 0) {
        float tot = 0.f;
#pragma unroll
        for (int i = 0; i < 8; i++) tot += sred[i];
        srs = rsqrtf(tot / (float)cols + EPSV);
    }
    __syncthreads();
    float rs = srs;
    for (int i = threadIdx.x; i < cols; i += 256)
        orow[i] = xr[i] * rs * w[i];
}

// ---------------- RoPE on q_pe, in place ------------------------------------
__global__ void __launch_bounds__(256) rope_q(
    float* __restrict__ q, const float* __restrict__ cosb, const float* __restrict__ sinb)
{
    int t = blockIdx.x;
    int h = blockIdx.y * 8 + (threadIdx.x >> 5);
    int i = threadIdx.x & 31;
    float* p = q + ((long long)t * NHEAD + h) * DHEAD + DNOPE;
    float a = p[2 * i], b = p[2 * i + 1];
    float c = cosb[t * 32 + i], s = sinb[t * 32 + i];
    __syncwarp();
    p[i]      = a * c - b * s;
    p[i + 32] = a * s + b * c;
}

// ---------------- assemble k_full: k_nope | broadcast(roped k_pe) -----------
__global__ void __launch_bounds__(256) build_kfull(
    const float* __restrict__ ckv, const float* __restrict__ kv,
    float* __restrict__ kf,
    const float* __restrict__ cosb, const float* __restrict__ sinb)
{
    int t = blockIdx.x;
    __shared__ float kpe[DROPE];
    if (threadIdx.x < 32) {
        int i = threadIdx.x;
        const float* kp = ckv + (long long)t * (KVRANK + DROPE) + KVRANK;
        float a = kp[2 * i], b = kp[2 * i + 1];
        float c = cosb[t * 32 + i], s = sinb[t * 32 + i];
        kpe[i]      = a * c - b * s;
        kpe[i + 32] = a * s + b * c;
    }
    __syncthreads();
    for (int idx = threadIdx.x; idx < NHEAD * DNOPE; idx += 256) {
        int h = idx >> 7, d = idx & 127;
        kf[((long long)t * NHEAD + h) * DHEAD + d] =
            kv[((long long)t * NHEAD + h) * (DNOPE + DV) + d];
    }
    for (int idx = threadIdx.x; idx < NHEAD * DROPE; idx += 256) {
        int h = idx >> 6, d = idx & 63;
        kf[((long long)t * NHEAD + h) * DHEAD + DNOPE + d] = kpe[d];
    }
}

// ---------------- causal softmax (scale fused), in place --------------------
__global__ void __launch_bounds__(256) softmax_causal(float* __restrict__ S)
{
    int t = blockIdx.x;
    long long h = blockIdx.y;
    float* row = S + (h * T_SEQ + t) * (long long)T_SEQ;
    int n = t + 1;
    int tid = threadIdx.x;
    float v[4];
#pragma unroll
    for (int j = 0; j < 4; j++) {
        int i = tid + j * 256;
        v[j] = (i < n) ? row[i] * SCALEV : -3.0e38f;
    }
    float m = fmaxf(fmaxf(v[0], v[1]), fmaxf(v[2], v[3]));
#pragma unroll
    for (int o = 16; o; o >>= 1) m = fmaxf(m, __shfl_xor_sync(0xffffffffu, m, o));
    __shared__ float sred[8];
    __shared__ float sres;
    if ((tid & 31) == 0) sred[tid >> 5] = m;
    __syncthreads();
    if (tid == 0) {
        float x = sred[0];
#pragma unroll
        for (int i = 1; i < 8; i++) x = fmaxf(x, sred[i]);
        sres = x;
    }
    __syncthreads();
    m = sres;
    __syncthreads();
    float s = 0.f;
#pragma unroll
    for (int j = 0; j < 4; j++) { v[j] = __expf(v[j] - m); s += v[j]; }
#pragma unroll
    for (int o = 16; o; o >>= 1) s += __shfl_xor_sync(0xffffffffu, s, o);
    if ((tid & 31) == 0) sred[tid >> 5] = s;
    __syncthreads();
    if (tid == 0) {
        float x = 0.f;
#pragma unroll
        for (int i = 0; i < 8; i++) x += sred[i];
        sres = x;
    }
    __syncthreads();
    float inv = 1.f / sres;
#pragma unroll
    for (int j = 0; j < 4; j++) {
        int i = tid + j * 256;
        row[i] = v[j] * inv;
    }
}

// ---------------- silu(gate) * up -------------------------------------------
__global__ void __launch_bounds__(256) silu_mul(
    const float* __restrict__ gu, float* __restrict__ y)
{
    long long idx = (long long)blockIdx.x * 256 + threadIdx.x;
    int t = (int)(idx / IFF);
    int i = (int)(idx % IFF);
    float g = gu[(long long)t * (2 * IFF) + i];
    float u = gu[(long long)t * (2 * IFF) + IFF + i];
    y[idx] = g / (1.f + __expf(-g)) * u;
}

// ---------------- launch ----------------------------------------------------
extern "C" void kernel_launch(void* const* d_in, const int* in_sizes, int n_in,
                              void* d_out, int out_size)
{
    const float* hidden    = (const float*)d_in[0];
    const float* cosb      = (const float*)d_in[1];
    const float* sinb      = (const float*)d_in[2];
    const float* w_ln_in   = (const float*)d_in[3];
    const float* w_q_a     = (const float*)d_in[4];
    const float* w_q_ln    = (const float*)d_in[5];
    const float* w_q_b     = (const float*)d_in[6];
    const float* w_kv_a    = (const float*)d_in[7];
    const float* w_kv_ln   = (const float*)d_in[8];
    const float* w_kv_b    = (const float*)d_in[9];
    const float* w_o       = (const float*)d_in[10];
    const float* w_ln_post = (const float*)d_in[11];
    const float* w_gate_up = (const float*)d_in[12];
    const float* w_down    = (const float*)d_in[13];
    float* out = (float*)d_out;

    static int smem_set = 0;
    if (!smem_set) {
        cudaFuncSetAttribute(gemm_tn_tf32,
                             cudaFuncAttributeMaxDynamicSharedMemorySize, GSMEM_SZ);
        smem_set = 1;
    }

    float *x, *qa, *qan, *q, *ckv, *cn, *kv, *kf, *vt, *sc, *ctx, *hres, *x2, *gu, *y;
    cudaGetSymbolAddress((void**)&x,    g_x);
    cudaGetSymbolAddress((void**)&qa,   g_qa);
    cudaGetSymbolAddress((void**)&qan,  g_qan);
    cudaGetSymbolAddress((void**)&q,    g_q);
    cudaGetSymbolAddress((void**)&ckv,  g_ckv);
    cudaGetSymbolAddress((void**)&cn,   g_cn);
    cudaGetSymbolAddress((void**)&kv,   g_kv);
    cudaGetSymbolAddress((void**)&kf,   g_kf);
    cudaGetSymbolAddress((void**)&vt,   g_vt);
    cudaGetSymbolAddress((void**)&sc,   g_sc);
    cudaGetSymbolAddress((void**)&ctx,  g_ctx);
    cudaGetSymbolAddress((void**)&hres, g_hres);
    cudaGetSymbolAddress((void**)&x2,   g_x2);
    cudaGetSymbolAddress((void**)&gu,   g_gu);
    cudaGetSymbolAddress((void**)&y,    g_y);

    // 1. x = rmsnorm(hidden)
    rmsnorm_k<<<T_SEQ, 256>>>(hidden, DMODEL, w_ln_in, x, DMODEL, DMODEL);
    // 2. q_a = x @ w_q_a^T
    gemm_tn_tf32<<<dim3(QRANK / 128, T_SEQ / 128, 1), 256, GSMEM_SZ>>>(
        x, DMODEL, 0, w_q_a, DMODEL, 0, qa, QRANK, 0, nullptr, QRANK, DMODEL, 0, 0);
    // 3. q_a = rmsnorm(q_a)
    rmsnorm_k<<<T_SEQ, 256>>>(qa, QRANK, w_q_ln, qan, QRANK, QRANK);
    // 4. q = q_a @ w_q_b^T  -> [T, H, 192]
    gemm_tn_tf32<<<dim3((NHEAD * DHEAD) / 128, T_SEQ / 128, 1), 256, GSMEM_SZ>>>(
        qan, QRANK, 0, w_q_b, QRANK, 0, q, NHEAD * DHEAD, 0, nullptr, NHEAD * DHEAD, QRANK, 0, 0);
    // 5. ckv = x @ w_kv_a^T  -> [T, 576]
    gemm_tn_tf32<<<dim3(5, T_SEQ / 128, 1), 256, GSMEM_SZ>>>(
        x, DMODEL, 0, w_kv_a, DMODEL, 0, ckv, KVRANK + DROPE, 0, nullptr, KVRANK + DROPE, DMODEL, 0, 0);
    // 6. c_n = rmsnorm(ckv[:, :512])
    rmsnorm_k<<<T_SEQ, 256>>>(ckv, KVRANK + DROPE, w_kv_ln, cn, KVRANK, KVRANK);
    // 7. kv = c_n @ w_kv_b^T -> [T, H, 256]
    gemm_tn_tf32<<<dim3((NHEAD * 256) / 128, T_SEQ / 128, 1), 256, GSMEM_SZ>>>(
        cn, KVRANK, 0, w_kv_b, KVRANK, 0, kv, NHEAD * 256, 0, nullptr, NHEAD * 256, KVRANK, 0, 0);
    // 8. rope q_pe in place
    rope_q<<<dim3(T_SEQ, NHEAD / 8), 256>>>(q, cosb, sinb);
    // 9. k_full
    build_kfull<<<T_SEQ, 256>>>(ckv, kv, kf, cosb, sinb);
    // 9b. vt = V^T per head
    transpose_v<<<dim3((NHEAD * DV) / 32, T_SEQ / 32), 256>>>(kv, vt);
    // 10. scores[h] = q[:,h,:] @ k_full[:,h,:]^T   (batched; causal-skip)
    gemm_tn_tf32<<<dim3(T_SEQ / 128, T_SEQ / 128, NHEAD), 256, GSMEM_SZ>>>(
        q, NHEAD * DHEAD, (long long)DHEAD,
        kf, NHEAD * DHEAD, (long long)DHEAD,
        sc, T_SEQ, (long long)T_SEQ * T_SEQ,
        nullptr, T_SEQ, DHEAD, 1, 0);
    // 11. causal softmax with scale (writes exact zeros above diagonal)
    softmax_causal<<<dim3(T_SEQ, NHEAD), 256>>>(sc);
    // 12. ctx[:,h,:] = probs[h] @ vt[h]^T  (TN, batched; K capped at m0+128)
    gemm_tn_tf32<<<dim3(1, T_SEQ / 128, NHEAD), 256, GSMEM_SZ>>>(
        sc, T_SEQ, (long long)T_SEQ * T_SEQ,
        vt, T_SEQ, (long long)DV * T_SEQ,
        ctx, NHEAD * DV, (long long)DV,
        nullptr, DV, T_SEQ, 0, 1);
    // 13. h_res = ctx @ w_o^T + hidden
    gemm_tn_tf32<<<dim3(DMODEL / 128, T_SEQ / 128, 1), 256, GSMEM_SZ>>>(
        ctx, DMODEL, 0, w_o, DMODEL, 0, hres, DMODEL, 0, hidden, DMODEL, DMODEL, 0, 0);
    // 14. x2 = rmsnorm(h_res)
    rmsnorm_k<<<T_SEQ, 256>>>(hres, DMODEL, w_ln_post, x2, DMODEL, DMODEL);
    // 15. gu = x2 @ w_gate_up^T -> [T, 2*IFF]
    gemm_tn_tf32<<<dim3((2 * IFF) / 128, T_SEQ / 128, 1), 256, GSMEM_SZ>>>(
        x2, DMODEL, 0, w_gate_up, DMODEL, 0, gu, 2 * IFF, 0, nullptr, 2 * IFF, DMODEL, 0, 0);
    // 16. y = silu(gate) * up
    silu_mul<<<(T_SEQ * IFF) / 256, 256>>>(gu, y);
    // 17. out = y @ w_down^T + h_res
    gemm_tn_tf32<<<dim3(DMODEL / 128, T_SEQ / 128, 1), 256, GSMEM_SZ>>>(
        y, IFF, 0, w_down, IFF, 0, out, DMODEL, 0, hres, DMODEL, IFF, 0, 0);
}